// round 1
// baseline (speedup 1.0000x reference)
#include <cuda_runtime.h>
#include <cstdint>
#include <cstddef>

#define N_TOT 262144
#define C_IN 128
#define C_OUT 128
#define K_OFF 27
#define TM 128
#define NBLK (N_TOT / TM)   // 2048
#define AP 132              // A smem pitch (floats): conflict-free A-frag reads
#define BP 136              // B smem pitch (floats): conflict-free B-frag reads
#define SMEM_BYTES ((TM * AP + C_IN * BP) * 4)

// Scratch (no allocations allowed): per-tile channel partials + BN params
__device__ float g_psum[NBLK * C_OUT];
__device__ float g_psq[NBLK * C_OUT];
__device__ float g_scale[C_OUT];
__device__ float g_shift[C_OUT];

__device__ __forceinline__ float tf32r(float f) {
    uint32_t u;
    asm("cvt.rna.tf32.f32 %0, %1;" : "=r"(u) : "f"(f));
    return __uint_as_float(u);
}

// ---------------------------------------------------------------------------
// Kernel 1: sparse conv. One CTA = one 128-row x 128-col output tile.
// Loop over 27 taps: gather A rows via rulebook, load W[k], tf32 warp MMA.
// ---------------------------------------------------------------------------
__global__ __launch_bounds__(256, 1) void conv_kernel(
    const float* __restrict__ feats,
    const float* __restrict__ W,
    const int*   __restrict__ nbr,
    float*       __restrict__ out)
{
    extern __shared__ float smem[];
    float* As = smem;             // [TM][AP]
    float* Bs = smem + TM * AP;   // [C_IN][BP]

    const int tid    = threadIdx.x;
    const int lane   = tid & 31;
    const int wid    = tid >> 5;        // 8 warps
    const int warp_m = wid & 3;         // 4 warps along M (32 rows each)
    const int warp_n = wid >> 2;        // 2 warps along N (64 cols each)
    const int base   = blockIdx.x * TM;

    const int gq = lane >> 2;  // group id 0..7
    const int tq = lane & 3;   // thread-in-group 0..3

    float acc[2][8][4];
#pragma unroll
    for (int i = 0; i < 2; i++)
#pragma unroll
        for (int j = 0; j < 8; j++)
#pragma unroll
            for (int c = 0; c < 4; c++) acc[i][j][c] = 0.f;

    for (int k = 0; k < K_OFF; ++k) {
        __syncthreads();  // previous compute done before smem overwrite

        // ---- load W[k] (128x128 f32, contiguous) into Bs[c][o], tf32-rounded
        const float4* Wk = (const float4*)(W + (size_t)k * C_IN * C_OUT);
#pragma unroll
        for (int i = tid; i < C_IN * C_OUT / 4; i += 256) {
            float4 v = Wk[i];
            int e   = i << 2;
            int row = e >> 7;      // c
            int col = e & 127;     // o
            float4 t;
            t.x = tf32r(v.x); t.y = tf32r(v.y); t.z = tf32r(v.z); t.w = tf32r(v.w);
            *(float4*)(Bs + row * BP + col) = t;
        }

        // ---- gather A: warp w loads rows w, w+8, ... (1 row = 1 coalesced 512B)
#pragma unroll
        for (int rr = 0; rr < TM / 8; ++rr) {
            int r   = wid + rr * 8;
            int idx = __ldg(&nbr[(size_t)(base + r) * K_OFF + k]);
            float4 v = make_float4(0.f, 0.f, 0.f, 0.f);
            if (idx >= 0)
                v = ((const float4*)(feats + (size_t)idx * C_IN))[lane];
            float4 t;
            t.x = tf32r(v.x); t.y = tf32r(v.y); t.z = tf32r(v.z); t.w = tf32r(v.w);
            *(float4*)(As + r * AP + (lane << 2)) = t;
        }
        __syncthreads();

        // ---- compute: 16 K-steps of m16n8k8 tf32, 2x8 frag grid per warp
#pragma unroll
        for (int kk = 0; kk < C_IN; kk += 8) {
            uint32_t a[2][4];
#pragma unroll
            for (int i = 0; i < 2; i++) {
                int r0 = warp_m * 32 + i * 16 + gq;
                a[i][0] = __float_as_uint(As[(r0    ) * AP + kk + tq    ]);
                a[i][1] = __float_as_uint(As[(r0 + 8) * AP + kk + tq    ]);
                a[i][2] = __float_as_uint(As[(r0    ) * AP + kk + tq + 4]);
                a[i][3] = __float_as_uint(As[(r0 + 8) * AP + kk + tq + 4]);
            }
#pragma unroll
            for (int j = 0; j < 8; j++) {
                int cb = warp_n * 64 + j * 8 + gq;
                uint32_t b0 = __float_as_uint(Bs[(kk + tq    ) * BP + cb]);
                uint32_t b1 = __float_as_uint(Bs[(kk + tq + 4) * BP + cb]);
#pragma unroll
                for (int i = 0; i < 2; i++) {
                    asm volatile(
                        "mma.sync.aligned.m16n8k8.row.col.f32.tf32.tf32.f32 "
                        "{%0,%1,%2,%3}, {%4,%5,%6,%7}, {%8,%9}, {%0,%1,%2,%3};"
                        : "+f"(acc[i][j][0]), "+f"(acc[i][j][1]),
                          "+f"(acc[i][j][2]), "+f"(acc[i][j][3])
                        : "r"(a[i][0]), "r"(a[i][1]), "r"(a[i][2]), "r"(a[i][3]),
                          "r"(b0), "r"(b1));
                }
            }
        }
    }

    // ---- epilogue: write raw conv output (BN applied later)
#pragma unroll
    for (int i = 0; i < 2; i++) {
        int r0 = base + warp_m * 32 + i * 16 + gq;
#pragma unroll
        for (int j = 0; j < 8; j++) {
            int c = warp_n * 64 + j * 8 + 2 * tq;
            *(float2*)(out + (size_t)r0 * C_OUT + c)       = make_float2(acc[i][j][0], acc[i][j][1]);
            *(float2*)(out + (size_t)(r0 + 8) * C_OUT + c) = make_float2(acc[i][j][2], acc[i][j][3]);
        }
    }
}

// ---------------------------------------------------------------------------
// Kernel 2: per-tile per-channel partial sum / sumsq (deterministic)
// ---------------------------------------------------------------------------
__global__ __launch_bounds__(128) void colsum_kernel(const float* __restrict__ out)
{
    const int c = threadIdx.x;
    const float* p = out + (size_t)blockIdx.x * TM * C_OUT;
    float s = 0.f, q = 0.f;
#pragma unroll 8
    for (int r = 0; r < TM; ++r) {
        float v = p[(size_t)r * C_OUT + c];
        s += v;
        q += v * v;
    }
    g_psum[blockIdx.x * C_OUT + c] = s;
    g_psq [blockIdx.x * C_OUT + c] = q;
}

// ---------------------------------------------------------------------------
// Kernel 3: reduce partials -> per-channel scale/shift
// ---------------------------------------------------------------------------
__global__ __launch_bounds__(128) void finalize_kernel(
    const float* __restrict__ gamma, const float* __restrict__ beta)
{
    const int c = threadIdx.x;
    float s = 0.f, q = 0.f;
#pragma unroll 4
    for (int b = 0; b < NBLK; ++b) {
        s += g_psum[b * C_OUT + c];
        q += g_psq [b * C_OUT + c];
    }
    const float inv_n = 1.f / (float)N_TOT;
    float mean = s * inv_n;
    float var  = q * inv_n - mean * mean;
    float sc   = gamma[c] * rsqrtf(var + 1e-4f);
    g_scale[c] = sc;
    g_shift[c] = beta[c] - mean * sc;
}

// ---------------------------------------------------------------------------
// Kernel 4: in-place normalize + leaky ReLU
// ---------------------------------------------------------------------------
__global__ __launch_bounds__(256) void norm_kernel(float* __restrict__ out)
{
    size_t i = (size_t)blockIdx.x * blockDim.x + threadIdx.x;
    float4 v = ((const float4*)out)[i];
    int c = (int)((i << 2) & (C_OUT - 1));
    float y;
    y = v.x * g_scale[c    ] + g_shift[c    ]; v.x = y > 0.f ? y : 0.333f * y;
    y = v.y * g_scale[c + 1] + g_shift[c + 1]; v.y = y > 0.f ? y : 0.333f * y;
    y = v.z * g_scale[c + 2] + g_shift[c + 2]; v.z = y > 0.f ? y : 0.333f * y;
    y = v.w * g_scale[c + 3] + g_shift[c + 3]; v.w = y > 0.f ? y : 0.333f * y;
    ((float4*)out)[i] = v;
}

// ---------------------------------------------------------------------------
// Launch. Inputs (metadata order): feats, W, gamma, beta, neighbor_idx.
// ---------------------------------------------------------------------------
extern "C" void kernel_launch(void* const* d_in, const int* in_sizes, int n_in,
                              void* d_out, int out_size)
{
    const float* feats = (const float*)d_in[0];
    const float* W     = (const float*)d_in[1];
    const float* gamma = (const float*)d_in[2];
    const float* beta  = (const float*)d_in[3];
    const int*   nbr   = (const int*)  d_in[4];
    float*       out   = (float*)d_out;

    cudaFuncSetAttribute(conv_kernel,
                         cudaFuncAttributeMaxDynamicSharedMemorySize, SMEM_BYTES);

    conv_kernel<<<NBLK, 256, SMEM_BYTES>>>(feats, W, nbr, out);
    colsum_kernel<<<NBLK, 128>>>(out);
    finalize_kernel<<<1, 128>>>(gamma, beta);
    norm_kernel<<<(N_TOT * C_OUT / 4) / 256, 256>>>(out);
}

// round 3
// speedup vs baseline: 1.9133x; 1.9133x over previous
#include <cuda_runtime.h>
#include <cuda_fp16.h>
#include <cstdint>
#include <cstddef>

// ---------------------------------------------------------------------------
// Problem constants
// ---------------------------------------------------------------------------
#define N_TOT 262144
#define CH    128          // C_in = C_out = 128
#define K_OFF 27
#define TM    128          // rows per CTA tile
#define NBLK  (N_TOT / TM) // 2048 CTAs

// A smem: 128 rows x 128 halfs, pitch 136 halfs (272B) -> conflict-free frag LDS
#define A_PITCH_B 272
#define A_BYTES   (TM * A_PITCH_B)          // 34816
#define B_BYTES   32768                     // 128x128 fp16, frag-ordered
#define STAGE_B   (A_BYTES + B_BYTES)       // 67584
#define SMEM_ALLOC (2 * STAGE_B)            // 135168

// ---------------------------------------------------------------------------
// Scratch (__device__ globals; no allocations allowed)
// ---------------------------------------------------------------------------
__device__ __half   g_fh[N_TOT * CH];              // fp16 feats (64 MB)
__device__ uint32_t g_Wh[K_OFF * 8192];            // fp16 W, frag-ordered
__device__ float    g_psum[NBLK * CH];
__device__ float    g_psq [NBLK * CH];
__device__ float    g_scale[CH];
__device__ float    g_shift[CH];

// ---------------------------------------------------------------------------
// cp.async helpers (Ampere+, valid in compute_100 PTX)
// ---------------------------------------------------------------------------
__device__ __forceinline__ void cp16(uint32_t dst, const void* src, int srcsize) {
    asm volatile("cp.async.cg.shared.global [%0], [%1], 16, %2;"
                 :: "r"(dst), "l"(src), "r"(srcsize) : "memory");
}
__device__ __forceinline__ void cp16f(uint32_t dst, const void* src) {
    asm volatile("cp.async.cg.shared.global [%0], [%1], 16;"
                 :: "r"(dst), "l"(src) : "memory");
}
#define CP_COMMIT() asm volatile("cp.async.commit_group;" ::: "memory")
#define CP_WAIT(n)  asm volatile("cp.async.wait_group %0;" :: "n"(n) : "memory")

__device__ __forceinline__ uint32_t smem_u32(const void* p) {
    uint32_t a;
    asm("{ .reg .u64 t; cvta.to.shared.u64 t, %1; cvt.u32.u64 %0, t; }"
        : "=r"(a) : "l"(p));
    return a;
}

// ---------------------------------------------------------------------------
// Kernel 0a: feats f32 -> fp16
// ---------------------------------------------------------------------------
__global__ __launch_bounds__(256) void prep_feats_kernel(const float* __restrict__ f)
{
    size_t e = (size_t)blockIdx.x * 256 + threadIdx.x;   // one per 8 floats
    const float4* src = (const float4*)f + e * 2;
    float4 v0 = __ldg(&src[0]);
    float4 v1 = __ldg(&src[1]);
    __half2 h0 = __floats2half2_rn(v0.x, v0.y);
    __half2 h1 = __floats2half2_rn(v0.z, v0.w);
    __half2 h2 = __floats2half2_rn(v1.x, v1.y);
    __half2 h3 = __floats2half2_rn(v1.z, v1.w);
    uint4 o;
    o.x = *(uint32_t*)&h0; o.y = *(uint32_t*)&h1;
    o.z = *(uint32_t*)&h2; o.w = *(uint32_t*)&h3;
    ((uint4*)g_fh)[e] = o;
}

// ---------------------------------------------------------------------------
// Kernel 0b: W f32 -> fp16, frag-ordered for mma.m16n8k16 B operand.
// Layout (uint32 units): [k][kstep s:8][nblock jj:16][lane t:32][reg r:2]
//   n  = jj*8 + t/4
//   kk = s*16 + (t%4)*2 + r*8   (pair kk, kk+1)
// ---------------------------------------------------------------------------
__global__ __launch_bounds__(256) void prep_w_kernel(const float* __restrict__ W)
{
    int e = blockIdx.x * 256 + threadIdx.x;   // one uint32 of g_Wh
    if (e >= K_OFF * 8192) return;
    int k   = e >> 13;
    int rem = e & 8191;
    int s   = rem >> 10;
    int jj  = (rem >> 6) & 15;
    int t   = (rem >> 1) & 31;
    int r   = e & 1;
    int n   = jj * 8 + (t >> 2);
    int kk  = s * 16 + (t & 3) * 2 + r * 8;
    const float* Wk = W + (size_t)k * CH * CH;
    __half2 h = __floats2half2_rn(Wk[kk * CH + n], Wk[(kk + 1) * CH + n]);
    g_Wh[e] = *(uint32_t*)&h;
}

// ---------------------------------------------------------------------------
// Kernel 1: sparse conv, fp16 m16n8k16 mma.sync, cp.async 2-stage pipeline.
// One CTA = 128 rows x 128 cols; 8 warps, warp tile 32(m) x 64(n).
// ---------------------------------------------------------------------------
__global__ __launch_bounds__(256, 1) void conv_kernel(
    const int*   __restrict__ nbr,
    float*       __restrict__ out)
{
    extern __shared__ char smem[];
    const uint32_t sm32 = smem_u32(smem);

    const int tid    = threadIdx.x;
    const int lane   = tid & 31;
    const int wid    = tid >> 5;
    const int warp_m = wid & 3;          // 4 warps over M (32 rows each)
    const int warp_n = wid >> 2;         // 2 warps over N (64 cols each)
    const int gq     = lane >> 2;
    const int tq     = lane & 3;
    const int base   = blockIdx.x * TM;

    // producer mapping: 2 threads per row, each loads one 128B half-row
    const int p_row  = tid >> 1;
    const int p_half = tid & 1;

    float acc[2][8][4];
#pragma unroll
    for (int i = 0; i < 2; i++)
#pragma unroll
        for (int j = 0; j < 8; j++)
#pragma unroll
            for (int c = 0; c < 4; c++) acc[i][j][c] = 0.f;

    // ---- issue loads for tap `k` into stage `st`
    auto issue = [&](int k, int st) {
        const uint32_t sA = sm32 + st * STAGE_B;
        const uint32_t sB = sA + A_BYTES;
        // A gather: this thread's half-row (8 x 16B), zero-fill when idx<0
        int idx = __ldg(&nbr[(size_t)(base + p_row) * K_OFF + k]);
        const char* srow = (const char*)g_fh
                         + ((size_t)(idx < 0 ? 0 : idx) << 8) + p_half * 128;
        uint32_t drow = sA + p_row * A_PITCH_B + p_half * 128;
        int sz = idx < 0 ? 0 : 16;
#pragma unroll
        for (int q = 0; q < 8; ++q) cp16(drow + q * 16, srow + q * 16, sz);
        // B: straight 32KB copy of frag-ordered weights
        const char* wsrc = (const char*)g_Wh + (size_t)k * 32768 + tid * 16;
        uint32_t wdst = sB + tid * 16;
#pragma unroll
        for (int q = 0; q < 8; ++q) cp16f(wdst + q * 4096, wsrc + q * 4096);
        CP_COMMIT();
    };

    issue(0, 0);

    for (int k = 0; k < K_OFF; ++k) {
        const int st = k & 1;
        if (k + 1 < K_OFF) { issue(k + 1, (k + 1) & 1); CP_WAIT(1); }
        else               { CP_WAIT(0); }
        __syncthreads();

        const uint32_t* Au = (const uint32_t*)(smem + st * STAGE_B);     // pitch 68 u32
        const uint32_t* Bu = (const uint32_t*)(smem + st * STAGE_B + A_BYTES);

#pragma unroll
        for (int s8 = 0; s8 < 8; ++s8) {
            uint32_t a[2][4];
#pragma unroll
            for (int i = 0; i < 2; ++i) {
                const uint32_t* p0 = Au + (warp_m * 32 + i * 16 + gq) * 68 + s8 * 8 + tq;
                a[i][0] = p0[0];
                a[i][1] = p0[8 * 68];
                a[i][2] = p0[4];
                a[i][3] = p0[8 * 68 + 4];
            }
#pragma unroll
            for (int j = 0; j < 8; ++j) {
                const uint2 b = *(const uint2*)(Bu + (s8 * 16 + warp_n * 8 + j) * 64 + lane * 2);
#pragma unroll
                for (int i = 0; i < 2; ++i) {
                    asm volatile(
                        "mma.sync.aligned.m16n8k16.row.col.f32.f16.f16.f32 "
                        "{%0,%1,%2,%3}, {%4,%5,%6,%7}, {%8,%9}, {%0,%1,%2,%3};"
                        : "+f"(acc[i][j][0]), "+f"(acc[i][j][1]),
                          "+f"(acc[i][j][2]), "+f"(acc[i][j][3])
                        : "r"(a[i][0]), "r"(a[i][1]), "r"(a[i][2]), "r"(a[i][3]),
                          "r"(b.x), "r"(b.y));
                }
            }
        }
        __syncthreads();
    }

    // ---- epilogue: write raw conv output (BN applied later)
#pragma unroll
    for (int i = 0; i < 2; i++) {
        int r0 = base + warp_m * 32 + i * 16 + gq;
#pragma unroll
        for (int j = 0; j < 8; j++) {
            int c = warp_n * 64 + j * 8 + 2 * tq;
            *(float2*)(out + (size_t)r0 * CH + c)       = make_float2(acc[i][j][0], acc[i][j][1]);
            *(float2*)(out + (size_t)(r0 + 8) * CH + c) = make_float2(acc[i][j][2], acc[i][j][3]);
        }
    }
}

// ---------------------------------------------------------------------------
// Kernel 2: per-tile per-channel partial sum / sumsq (deterministic)
// ---------------------------------------------------------------------------
__global__ __launch_bounds__(128) void colsum_kernel(const float* __restrict__ out)
{
    const int c = threadIdx.x;
    const float* p = out + (size_t)blockIdx.x * TM * CH;
    float s = 0.f, q = 0.f;
#pragma unroll 8
    for (int r = 0; r < TM; ++r) {
        float v = p[(size_t)r * CH + c];
        s += v;
        q += v * v;
    }
    g_psum[blockIdx.x * CH + c] = s;
    g_psq [blockIdx.x * CH + c] = q;
}

// ---------------------------------------------------------------------------
// Kernel 3: reduce partials -> per-channel scale/shift
// ---------------------------------------------------------------------------
__global__ __launch_bounds__(128) void finalize_kernel(
    const float* __restrict__ gamma, const float* __restrict__ beta)
{
    const int c = threadIdx.x;
    float s = 0.f, q = 0.f;
#pragma unroll 4
    for (int b = 0; b < NBLK; ++b) {
        s += g_psum[b * CH + c];
        q += g_psq [b * CH + c];
    }
    const float inv_n = 1.f / (float)N_TOT;
    float mean = s * inv_n;
    float var  = q * inv_n - mean * mean;
    float sc   = gamma[c] * rsqrtf(var + 1e-4f);
    g_scale[c] = sc;
    g_shift[c] = beta[c] - mean * sc;
}

// ---------------------------------------------------------------------------
// Kernel 4: in-place normalize + leaky ReLU
// ---------------------------------------------------------------------------
__global__ __launch_bounds__(256) void norm_kernel(float* __restrict__ out)
{
    size_t i = (size_t)blockIdx.x * blockDim.x + threadIdx.x;
    float4 v = ((const float4*)out)[i];
    int c = (int)((i << 2) & (CH - 1));
    float y;
    y = v.x * g_scale[c    ] + g_shift[c    ]; v.x = y > 0.f ? y : 0.333f * y;
    y = v.y * g_scale[c + 1] + g_shift[c + 1]; v.y = y > 0.f ? y : 0.333f * y;
    y = v.z * g_scale[c + 2] + g_shift[c + 2]; v.z = y > 0.f ? y : 0.333f * y;
    y = v.w * g_scale[c + 3] + g_shift[c + 3]; v.w = y > 0.f ? y : 0.333f * y;
    ((float4*)out)[i] = v;
}

// ---------------------------------------------------------------------------
// Launch. Inputs (metadata order): feats, W, gamma, beta, neighbor_idx.
// ---------------------------------------------------------------------------
extern "C" void kernel_launch(void* const* d_in, const int* in_sizes, int n_in,
                              void* d_out, int out_size)
{
    const float* feats = (const float*)d_in[0];
    const float* W     = (const float*)d_in[1];
    const float* gamma = (const float*)d_in[2];
    const float* beta  = (const float*)d_in[3];
    const int*   nbr   = (const int*)  d_in[4];
    float*       out   = (float*)d_out;

    cudaFuncSetAttribute(conv_kernel,
                         cudaFuncAttributeMaxDynamicSharedMemorySize, SMEM_ALLOC);

    prep_feats_kernel<<<N_TOT * CH / 8 / 256, 256>>>(feats);
    prep_w_kernel<<<(K_OFF * 8192 + 255) / 256, 256>>>(W);
    conv_kernel<<<NBLK, 256, SMEM_ALLOC>>>(nbr, out);
    colsum_kernel<<<NBLK, 128>>>(out);
    finalize_kernel<<<1, 128>>>(gamma, beta);
    norm_kernel<<<(N_TOT * CH / 4) / 256, 256>>>(out);
}

// round 4
// speedup vs baseline: 2.8915x; 1.5112x over previous
#include <cuda_runtime.h>
#include <cuda_fp16.h>
#include <cstdint>
#include <cstddef>

// ---------------------------------------------------------------------------
// Problem constants
// ---------------------------------------------------------------------------
#define N_TOT 262144
#define CH    128          // C_in = C_out = 128
#define K_OFF 27
#define TM    128          // rows per GEMM tile
#define NBLK  (N_TOT / TM) // 2048
#define NTAP  26           // taps excluding self (k=13)

// A smem: 128 rows x 128 halfs, pitch 136 halfs (272B) -> conflict-free frag LDS
#define A_PITCH_B 272
#define A_BYTES   (TM * A_PITCH_B)          // 34816
#define B_BYTES   32768                     // 128x128 fp16, frag-ordered
#define SMEM_ALLOC (A_BYTES + B_BYTES)      // 67584

// fixed-point accumulation
#define SCALE_F     4194304.0f              // 2^22
#define INV_SCALE_F 2.384185791015625e-07f  // 2^-22

// ---------------------------------------------------------------------------
// Scratch (__device__ globals; no allocations allowed)
// ---------------------------------------------------------------------------
__device__ __half   g_fh[N_TOT * CH];          // fp16 feats (64 MB)
__device__ uint32_t g_Wh[K_OFF * 8192];        // fp16 W, frag-ordered (884 KB)
__device__ int      g_acc[N_TOT * CH];         // int32 fixed-point accumulator
__device__ int2     g_list[(size_t)NTAP * N_TOT]; // per-tap pair lists (54 MB)
__device__ int      g_cnt[NTAP];
__device__ float    g_psum[NBLK * CH];
__device__ float    g_psq [NBLK * CH];
__device__ float    g_scale[CH];
__device__ float    g_shift[CH];

// ---------------------------------------------------------------------------
// helpers
// ---------------------------------------------------------------------------
__device__ __forceinline__ void cp16(uint32_t dst, const void* src, int srcsize) {
    asm volatile("cp.async.cg.shared.global [%0], [%1], 16, %2;"
                 :: "r"(dst), "l"(src), "r"(srcsize) : "memory");
}
__device__ __forceinline__ void cp16f(uint32_t dst, const void* src) {
    asm volatile("cp.async.cg.shared.global [%0], [%1], 16;"
                 :: "r"(dst), "l"(src) : "memory");
}
#define CP_COMMIT() asm volatile("cp.async.commit_group;" ::: "memory")
#define CP_WAIT0()  asm volatile("cp.async.wait_group 0;" ::: "memory")

__device__ __forceinline__ uint32_t smem_u32(const void* p) {
    uint32_t a;
    asm("{ .reg .u64 t; cvta.to.shared.u64 t, %1; cvt.u32.u64 %0, t; }"
        : "=r"(a) : "l"(p));
    return a;
}
__device__ __forceinline__ int f2i(float v) { return __float2int_rn(v * SCALE_F); }

// ---------------------------------------------------------------------------
// Kernel 0a: feats f32 -> fp16
// ---------------------------------------------------------------------------
__global__ __launch_bounds__(256) void prep_feats_kernel(const float* __restrict__ f)
{
    size_t e = (size_t)blockIdx.x * 256 + threadIdx.x;   // one per 8 floats
    const float4* src = (const float4*)f + e * 2;
    float4 v0 = __ldg(&src[0]);
    float4 v1 = __ldg(&src[1]);
    __half2 h0 = __floats2half2_rn(v0.x, v0.y);
    __half2 h1 = __floats2half2_rn(v0.z, v0.w);
    __half2 h2 = __floats2half2_rn(v1.x, v1.y);
    __half2 h3 = __floats2half2_rn(v1.z, v1.w);
    uint4 o;
    o.x = *(uint32_t*)&h0; o.y = *(uint32_t*)&h1;
    o.z = *(uint32_t*)&h2; o.w = *(uint32_t*)&h3;
    ((uint4*)g_fh)[e] = o;
}

// ---------------------------------------------------------------------------
// Kernel 0b: W f32 -> fp16, frag-ordered for mma.m16n8k16 B operand.
// Layout (uint32 units): [k][kstep s:8][nblock jj:16][lane t:32][reg r:2]
//   n = jj*8 + t/4 ; kk = s*16 + (t%4)*2 + r*8  (pair kk, kk+1)
// ---------------------------------------------------------------------------
__global__ __launch_bounds__(256) void prep_w_kernel(const float* __restrict__ W)
{
    int e = blockIdx.x * 256 + threadIdx.x;
    if (e >= K_OFF * 8192) return;
    int k   = e >> 13;
    int rem = e & 8191;
    int s   = rem >> 10;
    int jj  = (rem >> 6) & 15;
    int t   = (rem >> 1) & 31;
    int r   = e & 1;
    int n   = jj * 8 + (t >> 2);
    int kk  = s * 16 + (t & 3) * 2 + r * 8;
    const float* Wk = W + (size_t)k * CH * CH;
    __half2 h = __floats2half2_rn(Wk[kk * CH + n], Wk[(kk + 1) * CH + n]);
    g_Wh[e] = *(uint32_t*)&h;
}

// ---------------------------------------------------------------------------
// Kernel 0c: zero the 26 pair counters
// ---------------------------------------------------------------------------
__global__ void zero_cnt_kernel() {
    if (threadIdx.x < NTAP) g_cnt[threadIdx.x] = 0;
}

// ---------------------------------------------------------------------------
// Kernel 1: build per-tap compacted pair lists (skip self tap k=13).
// CTA = 256 rows; CTA-aggregated counter atomics + warp ballot scan.
// ---------------------------------------------------------------------------
__global__ __launch_bounds__(256) void build_kernel(const int* __restrict__ nbr)
{
    const int tid  = threadIdx.x;
    const int lane = tid & 31;
    const int wid  = tid >> 5;
    const int r    = blockIdx.x * 256 + tid;

    __shared__ int s_cnt [NTAP][8];
    __shared__ int s_base[NTAP][8];

    int idx[NTAP];
    unsigned msk[NTAP];
#pragma unroll
    for (int j = 0; j < NTAP; ++j) {
        int k = (j < 13) ? j : j + 1;
        idx[j] = __ldg(&nbr[(size_t)r * K_OFF + k]);
    }
#pragma unroll
    for (int j = 0; j < NTAP; ++j) {
        msk[j] = __ballot_sync(0xffffffffu, idx[j] >= 0);
        if (lane == 0) s_cnt[j][wid] = __popc(msk[j]);
    }
    __syncthreads();
    if (tid < NTAP) {
        int tot = 0, c[8];
#pragma unroll
        for (int w = 0; w < 8; ++w) { c[w] = tot; tot += s_cnt[tid][w]; }
        int base = atomicAdd(&g_cnt[tid], tot);
#pragma unroll
        for (int w = 0; w < 8; ++w) s_base[tid][w] = base + c[w];
    }
    __syncthreads();
#pragma unroll
    for (int j = 0; j < NTAP; ++j) {
        if (idx[j] >= 0) {
            int pos = s_base[j][wid] + __popc(msk[j] & ((1u << lane) - 1));
            g_list[(size_t)j * N_TOT + pos] = make_int2(r, idx[j]);
        }
    }
}

// ---------------------------------------------------------------------------
// Shared GEMM core: gather A (fp16 rows) + frag-ordered B, 8 k16 steps.
// ---------------------------------------------------------------------------
struct Frag { float a[2][8][4]; };

__device__ __forceinline__ void gemm_core(
    const char* smem, uint32_t sm32, int tid,
    const int* s_in, int tap, Frag& F)
{
    const int p_row  = tid >> 1;
    const int p_half = tid & 1;
    // A gather (zero-fill invalid rows)
    {
        int idx = s_in[p_row];
        const char* srow = (const char*)g_fh
                         + ((size_t)(idx < 0 ? 0 : idx) << 8) + p_half * 128;
        uint32_t drow = sm32 + p_row * A_PITCH_B + p_half * 128;
        int sz = idx < 0 ? 0 : 16;
#pragma unroll
        for (int q = 0; q < 8; ++q) cp16(drow + q * 16, srow + q * 16, sz);
    }
    // B copy
    {
        const char* wsrc = (const char*)g_Wh + (size_t)tap * 32768 + tid * 16;
        uint32_t wdst = sm32 + A_BYTES + tid * 16;
#pragma unroll
        for (int q = 0; q < 8; ++q) cp16f(wdst + q * 4096, wsrc + q * 4096);
    }
    CP_COMMIT();
    CP_WAIT0();
    __syncthreads();

    const int lane   = tid & 31;
    const int wid    = tid >> 5;
    const int warp_m = wid & 3;
    const int warp_n = wid >> 2;
    const int gq     = lane >> 2;
    const int tq     = lane & 3;
    const uint32_t* Au = (const uint32_t*)smem;              // pitch 68 u32
    const uint32_t* Bu = (const uint32_t*)(smem + A_BYTES);

#pragma unroll
    for (int s8 = 0; s8 < 8; ++s8) {
        uint32_t a[2][4];
#pragma unroll
        for (int i = 0; i < 2; ++i) {
            const uint32_t* p0 = Au + (warp_m * 32 + i * 16 + gq) * 68 + s8 * 8 + tq;
            a[i][0] = p0[0];
            a[i][1] = p0[8 * 68];
            a[i][2] = p0[4];
            a[i][3] = p0[8 * 68 + 4];
        }
#pragma unroll
        for (int j = 0; j < 8; ++j) {
            const uint2 b = *(const uint2*)(Bu + (s8 * 16 + warp_n * 8 + j) * 64 + lane * 2);
#pragma unroll
            for (int i = 0; i < 2; ++i) {
                asm volatile(
                    "mma.sync.aligned.m16n8k16.row.col.f32.f16.f16.f32 "
                    "{%0,%1,%2,%3}, {%4,%5,%6,%7}, {%8,%9}, {%0,%1,%2,%3};"
                    : "+f"(F.a[i][j][0]), "+f"(F.a[i][j][1]),
                      "+f"(F.a[i][j][2]), "+f"(F.a[i][j][3])
                    : "r"(a[i][0]), "r"(a[i][1]), "r"(a[i][2]), "r"(a[i][3]),
                      "r"(b.x), "r"(b.y));
            }
        }
    }
}

// ---------------------------------------------------------------------------
// Kernel 2: self-tap dense GEMM (k=13, nbr[r][13]==r) -> direct int32 store
// ---------------------------------------------------------------------------
__global__ __launch_bounds__(256, 2) void self_gemm_kernel()
{
    extern __shared__ char smem[];
    const uint32_t sm32 = smem_u32(smem);
    const int tid  = threadIdx.x;
    const int base = blockIdx.x * TM;

    __shared__ int s_in[TM];
    if (tid < TM) s_in[tid] = base + tid;
    __syncthreads();

    Frag F;
#pragma unroll
    for (int i = 0; i < 2; i++)
#pragma unroll
        for (int j = 0; j < 8; j++)
#pragma unroll
            for (int c = 0; c < 4; c++) F.a[i][j][c] = 0.f;

    gemm_core(smem, sm32, tid, s_in, 13, F);

    const int lane   = tid & 31;
    const int wid    = tid >> 5;
    const int warp_m = wid & 3;
    const int warp_n = wid >> 2;
    const int gq     = lane >> 2;
    const int tq     = lane & 3;
#pragma unroll
    for (int i = 0; i < 2; i++) {
        int r0 = base + warp_m * 32 + i * 16 + gq;
#pragma unroll
        for (int j = 0; j < 8; j++) {
            int c = warp_n * 64 + j * 8 + 2 * tq;
            *(int2*)&g_acc[(size_t)r0 * CH + c] =
                make_int2(f2i(F.a[i][j][0]), f2i(F.a[i][j][1]));
            *(int2*)&g_acc[(size_t)(r0 + 8) * CH + c] =
                make_int2(f2i(F.a[i][j][2]), f2i(F.a[i][j][3]));
        }
    }
}

// ---------------------------------------------------------------------------
// Kernel 3: scatter GEMM over compacted pair lists (26 taps), int32 red-add
// ---------------------------------------------------------------------------
__global__ __launch_bounds__(256, 2) void scat_gemm_kernel()
{
    const int j   = blockIdx.y;
    const int tap = (j < 13) ? j : j + 1;
    const int nk  = g_cnt[j];
    const int start = blockIdx.x * TM;
    if (start >= nk) return;

    extern __shared__ char smem[];
    const uint32_t sm32 = smem_u32(smem);
    const int tid = threadIdx.x;

    __shared__ int s_in[TM];
    __shared__ int s_out[TM];
    if (tid < TM) {
        int2 p = (start + tid < nk)
               ? __ldg(&g_list[(size_t)j * N_TOT + start + tid])
               : make_int2(-1, -1);
        s_out[tid] = p.x;
        s_in [tid] = p.y;
    }
    __syncthreads();

    Frag F;
#pragma unroll
    for (int i = 0; i < 2; i++)
#pragma unroll
        for (int jj = 0; jj < 8; jj++)
#pragma unroll
            for (int c = 0; c < 4; c++) F.a[i][jj][c] = 0.f;

    gemm_core(smem, sm32, tid, s_in, tap, F);

    const int lane   = tid & 31;
    const int wid    = tid >> 5;
    const int warp_m = wid & 3;
    const int warp_n = wid >> 2;
    const int gq     = lane >> 2;
    const int tq     = lane & 3;
#pragma unroll
    for (int i = 0; i < 2; i++) {
        int ra = warp_m * 32 + i * 16 + gq;
        int oa = s_out[ra];
        int ob = s_out[ra + 8];
#pragma unroll
        for (int jj = 0; jj < 8; jj++) {
            int c = warp_n * 64 + jj * 8 + 2 * tq;
            if (oa >= 0) {
                atomicAdd(&g_acc[(size_t)oa * CH + c],     f2i(F.a[i][jj][0]));
                atomicAdd(&g_acc[(size_t)oa * CH + c + 1], f2i(F.a[i][jj][1]));
            }
            if (ob >= 0) {
                atomicAdd(&g_acc[(size_t)ob * CH + c],     f2i(F.a[i][jj][2]));
                atomicAdd(&g_acc[(size_t)ob * CH + c + 1], f2i(F.a[i][jj][3]));
            }
        }
    }
}

// ---------------------------------------------------------------------------
// Kernel 4: per-tile per-channel partial sum / sumsq from int accumulator
// ---------------------------------------------------------------------------
__global__ __launch_bounds__(128) void colsum_kernel()
{
    const int c = threadIdx.x;
    const int* p = g_acc + (size_t)blockIdx.x * TM * CH;
    float s = 0.f, q = 0.f;
#pragma unroll 8
    for (int r = 0; r < TM; ++r) {
        float v = (float)p[(size_t)r * CH + c] * INV_SCALE_F;
        s += v;
        q += v * v;
    }
    g_psum[blockIdx.x * CH + c] = s;
    g_psq [blockIdx.x * CH + c] = q;
}

// ---------------------------------------------------------------------------
// Kernel 5: reduce partials -> per-channel scale/shift
// ---------------------------------------------------------------------------
__global__ __launch_bounds__(128) void finalize_kernel(
    const float* __restrict__ gamma, const float* __restrict__ beta)
{
    const int c = threadIdx.x;
    float s = 0.f, q = 0.f;
#pragma unroll 4
    for (int b = 0; b < NBLK; ++b) {
        s += g_psum[b * CH + c];
        q += g_psq [b * CH + c];
    }
    const float inv_n = 1.f / (float)N_TOT;
    float mean = s * inv_n;
    float var  = q * inv_n - mean * mean;
    float sc   = gamma[c] * rsqrtf(var + 1e-4f);
    g_scale[c] = sc;
    g_shift[c] = beta[c] - mean * sc;
}

// ---------------------------------------------------------------------------
// Kernel 6: normalize + leaky ReLU, int accumulator -> float out
// ---------------------------------------------------------------------------
__global__ __launch_bounds__(256) void norm_kernel(float* __restrict__ out)
{
    size_t i = (size_t)blockIdx.x * blockDim.x + threadIdx.x;
    int4 a = ((const int4*)g_acc)[i];
    int c = (int)((i << 2) & (CH - 1));
    float4 v;
    v.x = (float)a.x * INV_SCALE_F;
    v.y = (float)a.y * INV_SCALE_F;
    v.z = (float)a.z * INV_SCALE_F;
    v.w = (float)a.w * INV_SCALE_F;
    float y;
    y = v.x * g_scale[c    ] + g_shift[c    ]; v.x = y > 0.f ? y : 0.333f * y;
    y = v.y * g_scale[c + 1] + g_shift[c + 1]; v.y = y > 0.f ? y : 0.333f * y;
    y = v.z * g_scale[c + 2] + g_shift[c + 2]; v.z = y > 0.f ? y : 0.333f * y;
    y = v.w * g_scale[c + 3] + g_shift[c + 3]; v.w = y > 0.f ? y : 0.333f * y;
    ((float4*)out)[i] = v;
}

// ---------------------------------------------------------------------------
// Launch. Inputs (metadata order): feats, W, gamma, beta, neighbor_idx.
// ---------------------------------------------------------------------------
extern "C" void kernel_launch(void* const* d_in, const int* in_sizes, int n_in,
                              void* d_out, int out_size)
{
    const float* feats = (const float*)d_in[0];
    const float* W     = (const float*)d_in[1];
    const float* gamma = (const float*)d_in[2];
    const float* beta  = (const float*)d_in[3];
    const int*   nbr   = (const int*)  d_in[4];
    float*       out   = (float*)d_out;

    cudaFuncSetAttribute(self_gemm_kernel,
                         cudaFuncAttributeMaxDynamicSharedMemorySize, SMEM_ALLOC);
    cudaFuncSetAttribute(scat_gemm_kernel,
                         cudaFuncAttributeMaxDynamicSharedMemorySize, SMEM_ALLOC);

    prep_feats_kernel<<<N_TOT * CH / 8 / 256, 256>>>(feats);
    prep_w_kernel<<<(K_OFF * 8192 + 255) / 256, 256>>>(W);
    zero_cnt_kernel<<<1, 32>>>();
    build_kernel<<<N_TOT / 256, 256>>>(nbr);
    self_gemm_kernel<<<NBLK, 256, SMEM_ALLOC>>>();
    scat_gemm_kernel<<<dim3(NBLK, NTAP), 256, SMEM_ALLOC>>>();
    colsum_kernel<<<NBLK, 128>>>();
    finalize_kernel<<<1, 128>>>(gamma, beta);
    norm_kernel<<<(N_TOT * CH / 4) / 256, 256>>>(out);
}

// round 6
// speedup vs baseline: 3.4479x; 1.1925x over previous
#include <cuda_runtime.h>
#include <cuda_fp16.h>
#include <cstdint>
#include <cstddef>

// ---------------------------------------------------------------------------
// Problem constants
// ---------------------------------------------------------------------------
#define N_TOT 262144
#define CH    128          // C_in = C_out = 128
#define K_OFF 27
#define TM    128          // rows per GEMM tile
#define NBLK  (N_TOT / TM) // 2048
#define NTAP  26           // taps excluding self (k=13)
#define TILES_PER_TAP 320  // expected ~256 tiles/tap; ~30-sigma margin

// A smem: 128 rows x 128 halfs, pitch 136 halfs (272B) -> conflict-free frag LDS
#define A_PITCH_B 272
#define A_BYTES   (TM * A_PITCH_B)          // 34816
#define B_BYTES   32768                     // 128x128 fp16, frag-ordered
#define SMEM_ALLOC (A_BYTES + B_BYTES)      // 67584 (also >= 64KB staging union)

// fixed-point accumulation
#define SCALE_F     4194304.0f              // 2^22
#define INV_SCALE_F 2.384185791015625e-07f  // 2^-22

// ---------------------------------------------------------------------------
// Scratch (__device__ globals; no allocations allowed)
// ---------------------------------------------------------------------------
__device__ __half   g_fh[N_TOT * CH];             // fp16 feats (64 MB)
__device__ uint32_t g_Wh[K_OFF * 8192];           // fp16 W, frag-ordered
__device__ int      g_acc[N_TOT * CH];            // int32 fixed-point accumulator
__device__ int2     g_list[(size_t)NTAP * N_TOT]; // per-tap pair lists
__device__ int      g_cnt[NTAP];
__device__ float    g_psum[NBLK * CH];
__device__ float    g_psq [NBLK * CH];
__device__ float    g_scale[CH];
__device__ float    g_shift[CH];

// ---------------------------------------------------------------------------
// helpers
// ---------------------------------------------------------------------------
__device__ __forceinline__ void cp16(uint32_t dst, const void* src, int srcsize) {
    asm volatile("cp.async.cg.shared.global [%0], [%1], 16, %2;"
                 :: "r"(dst), "l"(src), "r"(srcsize) : "memory");
}
__device__ __forceinline__ void cp16f(uint32_t dst, const void* src) {
    asm volatile("cp.async.cg.shared.global [%0], [%1], 16;"
                 :: "r"(dst), "l"(src) : "memory");
}
#define CP_COMMIT() asm volatile("cp.async.commit_group;" ::: "memory")
#define CP_WAIT0()  asm volatile("cp.async.wait_group 0;" ::: "memory")

// bulk int32 add-reduce: 512B smem row -> global (Hopper+; base sm_90 feature)
__device__ __forceinline__ void red_bulk_512(void* gdst, uint32_t ssrc) {
    asm volatile(
        "cp.reduce.async.bulk.global.shared::cta.bulk_group.add.u32 [%0], [%1], 512;"
        :: "l"(gdst), "r"(ssrc) : "memory");
}
#define BULK_COMMIT() asm volatile("cp.async.bulk.commit_group;" ::: "memory")
#define BULK_WAIT0()  asm volatile("cp.async.bulk.wait_group 0;" ::: "memory")
#define FENCE_PROXY_ASYNC() \
    asm volatile("fence.proxy.async.shared::cta;" ::: "memory")

__device__ __forceinline__ uint32_t smem_u32(const void* p) {
    uint32_t a;
    asm("{ .reg .u64 t; cvta.to.shared.u64 t, %1; cvt.u32.u64 %0, t; }"
        : "=r"(a) : "l"(p));
    return a;
}
__device__ __forceinline__ int f2i(float v) { return __float2int_rn(v * SCALE_F); }

// ---------------------------------------------------------------------------
// Kernel 0a: feats f32 -> fp16
// ---------------------------------------------------------------------------
__global__ __launch_bounds__(256) void prep_feats_kernel(const float* __restrict__ f)
{
    size_t e = (size_t)blockIdx.x * 256 + threadIdx.x;   // one per 8 floats
    const float4* src = (const float4*)f + e * 2;
    float4 v0 = __ldg(&src[0]);
    float4 v1 = __ldg(&src[1]);
    __half2 h0 = __floats2half2_rn(v0.x, v0.y);
    __half2 h1 = __floats2half2_rn(v0.z, v0.w);
    __half2 h2 = __floats2half2_rn(v1.x, v1.y);
    __half2 h3 = __floats2half2_rn(v1.z, v1.w);
    uint4 o;
    o.x = *(uint32_t*)&h0; o.y = *(uint32_t*)&h1;
    o.z = *(uint32_t*)&h2; o.w = *(uint32_t*)&h3;
    ((uint4*)g_fh)[e] = o;
}

// ---------------------------------------------------------------------------
// Kernel 0b: W f32 -> fp16, frag-ordered for mma.m16n8k16 B operand.
//   n = jj*8 + t/4 ; kk = s*16 + (t%4)*2 + r*8  (pair kk, kk+1)
// ---------------------------------------------------------------------------
__global__ __launch_bounds__(256) void prep_w_kernel(const float* __restrict__ W)
{
    int e = blockIdx.x * 256 + threadIdx.x;
    if (e >= K_OFF * 8192) return;
    int k   = e >> 13;
    int rem = e & 8191;
    int s   = rem >> 10;
    int jj  = (rem >> 6) & 15;
    int t   = (rem >> 1) & 31;
    int r   = e & 1;
    int n   = jj * 8 + (t >> 2);
    int kk  = s * 16 + (t & 3) * 2 + r * 8;
    const float* Wk = W + (size_t)k * CH * CH;
    __half2 h = __floats2half2_rn(Wk[kk * CH + n], Wk[(kk + 1) * CH + n]);
    g_Wh[e] = *(uint32_t*)&h;
}

// ---------------------------------------------------------------------------
// Kernel 0c: zero the 26 pair counters
// ---------------------------------------------------------------------------
__global__ void zero_cnt_kernel() {
    if (threadIdx.x < NTAP) g_cnt[threadIdx.x] = 0;
}

// ---------------------------------------------------------------------------
// Kernel 1: build per-tap compacted pair lists (skip self tap k=13).
// ---------------------------------------------------------------------------
__global__ __launch_bounds__(256) void build_kernel(const int* __restrict__ nbr)
{
    const int tid  = threadIdx.x;
    const int lane = tid & 31;
    const int wid  = tid >> 5;
    const int r    = blockIdx.x * 256 + tid;

    __shared__ int s_cnt [NTAP][8];
    __shared__ int s_base[NTAP][8];

    int idx[NTAP];
    unsigned msk[NTAP];
#pragma unroll
    for (int j = 0; j < NTAP; ++j) {
        int k = (j < 13) ? j : j + 1;
        idx[j] = __ldg(&nbr[(size_t)r * K_OFF + k]);
    }
#pragma unroll
    for (int j = 0; j < NTAP; ++j) {
        msk[j] = __ballot_sync(0xffffffffu, idx[j] >= 0);
        if (lane == 0) s_cnt[j][wid] = __popc(msk[j]);
    }
    __syncthreads();
    if (tid < NTAP) {
        int tot = 0, c[8];
#pragma unroll
        for (int w = 0; w < 8; ++w) { c[w] = tot; tot += s_cnt[tid][w]; }
        int base = atomicAdd(&g_cnt[tid], tot);
#pragma unroll
        for (int w = 0; w < 8; ++w) s_base[tid][w] = base + c[w];
    }
    __syncthreads();
#pragma unroll
    for (int j = 0; j < NTAP; ++j) {
        if (idx[j] >= 0) {
            int pos = s_base[j][wid] + __popc(msk[j] & ((1u << lane) - 1));
            g_list[(size_t)j * N_TOT + pos] = make_int2(r, idx[j]);
        }
    }
}

// ---------------------------------------------------------------------------
// Shared GEMM core: gather A (fp16 rows) + frag-ordered B, 8 k16 steps.
// ---------------------------------------------------------------------------
struct Frag { float a[2][8][4]; };

__device__ __forceinline__ void gemm_core(
    const char* smem, uint32_t sm32, int tid,
    const int* s_in, int tap, Frag& F)
{
    const int p_row  = tid >> 1;
    const int p_half = tid & 1;
    // A gather (zero-fill invalid rows)
    {
        int idx = s_in[p_row];
        const char* srow = (const char*)g_fh
                         + ((size_t)(idx < 0 ? 0 : idx) << 8) + p_half * 128;
        uint32_t drow = sm32 + p_row * A_PITCH_B + p_half * 128;
        int sz = idx < 0 ? 0 : 16;
#pragma unroll
        for (int q = 0; q < 8; ++q) cp16(drow + q * 16, srow + q * 16, sz);
    }
    // B copy
    {
        const char* wsrc = (const char*)g_Wh + (size_t)tap * 32768 + tid * 16;
        uint32_t wdst = sm32 + A_BYTES + tid * 16;
#pragma unroll
        for (int q = 0; q < 8; ++q) cp16f(wdst + q * 4096, wsrc + q * 4096);
    }
    CP_COMMIT();
    CP_WAIT0();
    __syncthreads();

    const int lane   = tid & 31;
    const int wid    = tid >> 5;
    const int warp_m = wid & 3;
    const int warp_n = wid >> 2;
    const int gq     = lane >> 2;
    const int tq     = lane & 3;
    const uint32_t* Au = (const uint32_t*)smem;              // pitch 68 u32
    const uint32_t* Bu = (const uint32_t*)(smem + A_BYTES);

#pragma unroll
    for (int s8 = 0; s8 < 8; ++s8) {
        uint32_t a[2][4];
#pragma unroll
        for (int i = 0; i < 2; ++i) {
            const uint32_t* p0 = Au + (warp_m * 32 + i * 16 + gq) * 68 + s8 * 8 + tq;
            a[i][0] = p0[0];
            a[i][1] = p0[8 * 68];
            a[i][2] = p0[4];
            a[i][3] = p0[8 * 68 + 4];
        }
#pragma unroll
        for (int j = 0; j < 8; ++j) {
            const uint2 b = *(const uint2*)(Bu + (s8 * 16 + warp_n * 8 + j) * 64 + lane * 2);
#pragma unroll
            for (int i = 0; i < 2; ++i) {
                asm volatile(
                    "mma.sync.aligned.m16n8k16.row.col.f32.f16.f16.f32 "
                    "{%0,%1,%2,%3}, {%4,%5,%6,%7}, {%8,%9}, {%0,%1,%2,%3};"
                    : "+f"(F.a[i][j][0]), "+f"(F.a[i][j][1]),
                      "+f"(F.a[i][j][2]), "+f"(F.a[i][j][3])
                    : "r"(a[i][0]), "r"(a[i][1]), "r"(a[i][2]), "r"(a[i][3]),
                      "r"(b.x), "r"(b.y));
            }
        }
    }
}

// ---------------------------------------------------------------------------
// Kernel 2: self-tap dense GEMM (k=13, nbr[r][13]==r) -> direct int32 store
// ---------------------------------------------------------------------------
__global__ __launch_bounds__(256, 2) void self_gemm_kernel()
{
    extern __shared__ char smem[];
    const uint32_t sm32 = smem_u32(smem);
    const int tid  = threadIdx.x;
    const int base = blockIdx.x * TM;

    __shared__ int s_in[TM];
    if (tid < TM) s_in[tid] = base + tid;
    __syncthreads();

    Frag F;
#pragma unroll
    for (int i = 0; i < 2; i++)
#pragma unroll
        for (int j = 0; j < 8; j++)
#pragma unroll
            for (int c = 0; c < 4; c++) F.a[i][j][c] = 0.f;

    gemm_core(smem, sm32, tid, s_in, 13, F);

    const int lane   = tid & 31;
    const int wid    = tid >> 5;
    const int warp_m = wid & 3;
    const int warp_n = wid >> 2;
    const int gq     = lane >> 2;
    const int tq     = lane & 3;
#pragma unroll
    for (int i = 0; i < 2; i++) {
        int r0 = base + warp_m * 32 + i * 16 + gq;
#pragma unroll
        for (int j = 0; j < 8; j++) {
            int c = warp_n * 64 + j * 8 + 2 * tq;
            *(int2*)&g_acc[(size_t)r0 * CH + c] =
                make_int2(f2i(F.a[i][j][0]), f2i(F.a[i][j][1]));
            *(int2*)&g_acc[(size_t)(r0 + 8) * CH + c] =
                make_int2(f2i(F.a[i][j][2]), f2i(F.a[i][j][3]));
        }
    }
}

// ---------------------------------------------------------------------------
// Kernel 3: scatter GEMM over compacted pair lists (26 taps).
// Epilogue: stage int32 tile in smem, then ONE 512B bulk add-reduce per row.
// ---------------------------------------------------------------------------
__global__ __launch_bounds__(256, 2) void scat_gemm_kernel()
{
    const int j   = blockIdx.y;
    const int tap = (j < 13) ? j : j + 1;
    const int nk  = g_cnt[j];
    const int start = blockIdx.x * TM;
    if (start >= nk) return;

    extern __shared__ char smem[];
    const uint32_t sm32 = smem_u32(smem);
    const int tid = threadIdx.x;

    __shared__ int s_in[TM];
    __shared__ int s_out[TM];
    if (tid < TM) {
        int2 p = (start + tid < nk)
               ? __ldg(&g_list[(size_t)j * N_TOT + start + tid])
               : make_int2(-1, -1);
        s_out[tid] = p.x;
        s_in [tid] = p.y;
    }
    __syncthreads();

    Frag F;
#pragma unroll
    for (int i = 0; i < 2; i++)
#pragma unroll
        for (int jj = 0; jj < 8; jj++)
#pragma unroll
            for (int c = 0; c < 4; c++) F.a[i][jj][c] = 0.f;

    gemm_core(smem, sm32, tid, s_in, tap, F);
    __syncthreads();   // MMA reads done before smem reuse as staging

    // ---- stage int32 tile into smem (overlays A/B region; 64KB)
    int* S = (int*)smem;
    const int lane   = tid & 31;
    const int wid    = tid >> 5;
    const int warp_m = wid & 3;
    const int warp_n = wid >> 2;
    const int gq     = lane >> 2;
    const int tq     = lane & 3;
#pragma unroll
    for (int i = 0; i < 2; i++) {
        int ra = warp_m * 32 + i * 16 + gq;
#pragma unroll
        for (int jj = 0; jj < 8; jj++) {
            int c = warp_n * 64 + jj * 8 + 2 * tq;
            *(int2*)&S[ra * CH + c] =
                make_int2(f2i(F.a[i][jj][0]), f2i(F.a[i][jj][1]));
            *(int2*)&S[(ra + 8) * CH + c] =
                make_int2(f2i(F.a[i][jj][2]), f2i(F.a[i][jj][3]));
        }
    }
    __syncthreads();

    // ---- one bulk add-reduce (512B) per valid output row
    if (tid < TM) {
        int o = s_out[tid];
        if (o >= 0) {
            FENCE_PROXY_ASYNC();
            red_bulk_512(&g_acc[(size_t)o * CH], sm32 + tid * 512);
            BULK_COMMIT();
            BULK_WAIT0();
        }
    }
}

// ---------------------------------------------------------------------------
// Kernel 4: per-tile per-channel partial sum / sumsq from int accumulator
// ---------------------------------------------------------------------------
__global__ __launch_bounds__(128) void colsum_kernel()
{
    const int c = threadIdx.x;
    const int* p = g_acc + (size_t)blockIdx.x * TM * CH;
    float s = 0.f, q = 0.f;
#pragma unroll 8
    for (int r = 0; r < TM; ++r) {
        float v = (float)p[(size_t)r * CH + c] * INV_SCALE_F;
        s += v;
        q += v * v;
    }
    g_psum[blockIdx.x * CH + c] = s;
    g_psq [blockIdx.x * CH + c] = q;
}

// ---------------------------------------------------------------------------
// Kernel 5: reduce partials -> per-channel scale/shift
// ---------------------------------------------------------------------------
__global__ __launch_bounds__(128) void finalize_kernel(
    const float* __restrict__ gamma, const float* __restrict__ beta)
{
    const int c = threadIdx.x;
    float s = 0.f, q = 0.f;
#pragma unroll 4
    for (int b = 0; b < NBLK; ++b) {
        s += g_psum[b * CH + c];
        q += g_psq [b * CH + c];
    }
    const float inv_n = 1.f / (float)N_TOT;
    float mean = s * inv_n;
    float var  = q * inv_n - mean * mean;
    float sc   = gamma[c] * rsqrtf(var + 1e-4f);
    g_scale[c] = sc;
    g_shift[c] = beta[c] - mean * sc;
}

// ---------------------------------------------------------------------------
// Kernel 6: normalize + leaky ReLU, int accumulator -> float out
// ---------------------------------------------------------------------------
__global__ __launch_bounds__(256) void norm_kernel(float* __restrict__ out)
{
    size_t i = (size_t)blockIdx.x * blockDim.x + threadIdx.x;
    int4 a = ((const int4*)g_acc)[i];
    int c = (int)((i << 2) & (CH - 1));
    float4 v;
    v.x = (float)a.x * INV_SCALE_F;
    v.y = (float)a.y * INV_SCALE_F;
    v.z = (float)a.z * INV_SCALE_F;
    v.w = (float)a.w * INV_SCALE_F;
    float y;
    y = v.x * g_scale[c    ] + g_shift[c    ]; v.x = y > 0.f ? y : 0.333f * y;
    y = v.y * g_scale[c + 1] + g_shift[c + 1]; v.y = y > 0.f ? y : 0.333f * y;
    y = v.z * g_scale[c + 2] + g_shift[c + 2]; v.z = y > 0.f ? y : 0.333f * y;
    y = v.w * g_scale[c + 3] + g_shift[c + 3]; v.w = y > 0.f ? y : 0.333f * y;
    ((float4*)out)[i] = v;
}

// ---------------------------------------------------------------------------
// Launch. Inputs (metadata order): feats, W, gamma, beta, neighbor_idx.
// ---------------------------------------------------------------------------
extern "C" void kernel_launch(void* const* d_in, const int* in_sizes, int n_in,
                              void* d_out, int out_size)
{
    const float* feats = (const float*)d_in[0];
    const float* W     = (const float*)d_in[1];
    const float* gamma = (const float*)d_in[2];
    const float* beta  = (const float*)d_in[3];
    const int*   nbr   = (const int*)  d_in[4];
    float*       out   = (float*)d_out;

    cudaFuncSetAttribute(self_gemm_kernel,
                         cudaFuncAttributeMaxDynamicSharedMemorySize, SMEM_ALLOC);
    cudaFuncSetAttribute(scat_gemm_kernel,
                         cudaFuncAttributeMaxDynamicSharedMemorySize, SMEM_ALLOC);

    prep_feats_kernel<<<N_TOT * CH / 8 / 256, 256>>>(feats);
    prep_w_kernel<<<(K_OFF * 8192 + 255) / 256, 256>>>(W);
    zero_cnt_kernel<<<1, 32>>>();
    build_kernel<<<N_TOT / 256, 256>>>(nbr);
    self_gemm_kernel<<<NBLK, 256, SMEM_ALLOC>>>();
    scat_gemm_kernel<<<dim3(TILES_PER_TAP, NTAP), 256, SMEM_ALLOC>>>();
    colsum_kernel<<<NBLK, 128>>>();
    finalize_kernel<<<1, 128>>>(gamma, beta);
    norm_kernel<<<(N_TOT * CH / 4) / 256, 256>>>(out);
}